// round 10
// baseline (speedup 1.0000x reference)
#include <cuda_runtime.h>
#include <cuda_fp16.h>
#include <cstdint>

#define D_DIM 768
#define V_OFF (10240*768)
#define TBM 128
#define TBN 64
#define NSTG 12                  // K stages of 64 halfs
#define ASTG 16384               // 128 rows * 128B
#define BSTG 8192                // 64 rows * 128B
#define THREADS 384              // 8 consumer warps + 4 producer warps
#define POS_OFF (2*ASTG + 2*BSTG)          // 49152
#define SMEM_TOTAL (POS_OFF + 128*12)

__device__ __half g_Bh[D_DIM*D_DIM];     // rn_f16(W), row-major (d, f)

__device__ __forceinline__ uint32_t smem_u32(const void* p){
  uint32_t a;
  asm("{ .reg .u64 t; cvta.to.shared.u64 t, %1; cvt.u32.u64 %0, t; }" : "=r"(a) : "l"(p));
  return a;
}
__device__ __forceinline__ void mma16(float* c, const uint32_t* a, uint32_t b0, uint32_t b1){
  asm volatile(
    "mma.sync.aligned.m16n8k16.row.col.f32.f16.f16.f32 "
    "{%0,%1,%2,%3},{%4,%5,%6,%7},{%8,%9},{%0,%1,%2,%3};\n"
    : "+f"(c[0]), "+f"(c[1]), "+f"(c[2]), "+f"(c[3])
    : "r"(a[0]), "r"(a[1]), "r"(a[2]), "r"(a[3]), "r"(b0), "r"(b1));
}
__device__ __forceinline__ void ldsm4(uint32_t* r, uint32_t addr){
  asm volatile("ldmatrix.sync.aligned.m8n8.x4.shared.b16 {%0,%1,%2,%3}, [%4];"
    : "=r"(r[0]), "=r"(r[1]), "=r"(r[2]), "=r"(r[3]) : "r"(addr));
}
__device__ __forceinline__ void cpasync16(uint32_t dst, const void* src){
  asm volatile("cp.async.cg.shared.global [%0], [%1], 16;"
               :: "r"(dst), "l"(src) : "memory");
}
__device__ __forceinline__ uint32_t pack2(float x, float y){
  __half2 h = __floats2half2_rn(x, y);
  return *reinterpret_cast<uint32_t*>(&h);
}

// ---- prep: g_Bh = rn_f16(W), coalesced ----
__global__ void __launch_bounds__(256) prep_b(const float* __restrict__ w){
  const int q = blockIdx.x*256 + threadIdx.x;     // 16B output chunks
  const float4* s4 = reinterpret_cast<const float4*>(w) + q*2;
  float4 v0 = s4[0], v1 = s4[1];
  uint4 u;
  u.x = pack2(v0.x, v0.y); u.y = pack2(v0.z, v0.w);
  u.z = pack2(v1.x, v1.y); u.w = pack2(v1.z, v1.w);
  reinterpret_cast<uint4*>(g_Bh)[q] = u;
}

// ---- fused GEMM: producer warps convert pixels in-kernel ----
__global__ void __launch_bounds__(THREADS, 2)
gemma4_patch_embed(const float* __restrict__ pix,      // (16,3,512,512)
                   const float* __restrict__ ptab,     // (2,10240,768)
                   const int*   __restrict__ pids,     // (16,1024,2)
                   const int*   __restrict__ padp,     // (16,1024) bool-as-i32
                   float* __restrict__ out)            // (16,1024,768)
{
  extern __shared__ char smem[];
  const uint32_t sA = smem_u32(smem);             // 2 x ASTG
  const uint32_t sB = sA + 2*ASTG;                // 2 x BSTG
  int*   sO0 = reinterpret_cast<int*>(smem + POS_OFF);
  int*   sO1 = sO0 + 128;
  float* sPm = reinterpret_cast<float*>(sO1 + 128);
  const int t  = threadIdx.x;
  const int m0 = blockIdx.y * TBM;
  const int n0 = blockIdx.x * TBN;

  if (t < TBM) {
    const int m = m0 + t;
    int x = pids[2*m];     if (x < 0) x = 0;
    int y = pids[2*m + 1]; if (y < 0) y = 0;
    sO0[t] = x * D_DIM;
    sO1[t] = V_OFF + y * D_DIM;
    sPm[t] = (padp[m] != 0) ? 0.f : 1.f;
  }

  if (t >= 256) {
    // ==================== PRODUCER warps (4) ====================
    const int pt = t - 256;                 // 0..127 == A row
    // A source: row m = m0+pt
    const int m = m0 + pt;
    const int b = m >> 10, n = m & 1023;
    const float* pixRow = pix + b*786432 + (n >> 5)*8192 + (n & 31)*16;
    // A STS: row pt, units 0..7 swizzled
    uint32_t aDst[8];
    #pragma unroll
    for (int u = 0; u < 8; u++)
      aDst[u] = pt*128 + ((u ^ (pt & 7)) << 4);
    // B: row pt>>1, 4 units
    const int rB  = pt >> 1;
    const int ubB = (pt & 1) * 4;
    const __half* bSrc0 = g_Bh + (n0 + rB)*D_DIM + ubB*8;
    uint32_t bDst[4];
    #pragma unroll
    for (int u = 0; u < 4; u++)
      bDst[u] = rB*128 + (((ubB + u) ^ (rB & 7)) << 4);

    float4 aR[4][4];      // 4 (c,r) rows x 16 f32
    auto ldgA = [&](int s){
      const int c  = s >> 2;
      const int r0 = (s & 3) * 4;
      const float* src = pixRow + c*262144 + r0*512;
      #pragma unroll
      for (int j = 0; j < 4; j++) {
        const float* p = src + j*512;
        aR[j][0] = *reinterpret_cast<const float4*>(p);
        aR[j][1] = *reinterpret_cast<const float4*>(p + 4);
        aR[j][2] = *reinterpret_cast<const float4*>(p + 8);
        aR[j][3] = *reinterpret_cast<const float4*>(p + 12);
      }
    };
    auto stsA = [&](int s){
      const uint32_t aB = sA + (s & 1)*ASTG;
      #pragma unroll
      for (int j = 0; j < 4; j++) {
        uint4 u0, u1;
        u0.x = pack2(fmaf(2.f,aR[j][0].x,-1.f), fmaf(2.f,aR[j][0].y,-1.f));
        u0.y = pack2(fmaf(2.f,aR[j][0].z,-1.f), fmaf(2.f,aR[j][0].w,-1.f));
        u0.z = pack2(fmaf(2.f,aR[j][1].x,-1.f), fmaf(2.f,aR[j][1].y,-1.f));
        u0.w = pack2(fmaf(2.f,aR[j][1].z,-1.f), fmaf(2.f,aR[j][1].w,-1.f));
        u1.x = pack2(fmaf(2.f,aR[j][2].x,-1.f), fmaf(2.f,aR[j][2].y,-1.f));
        u1.y = pack2(fmaf(2.f,aR[j][2].z,-1.f), fmaf(2.f,aR[j][2].w,-1.f));
        u1.z = pack2(fmaf(2.f,aR[j][3].x,-1.f), fmaf(2.f,aR[j][3].y,-1.f));
        u1.w = pack2(fmaf(2.f,aR[j][3].z,-1.f), fmaf(2.f,aR[j][3].w,-1.f));
        asm volatile("st.shared.v4.b32 [%0], {%1,%2,%3,%4};" ::
          "r"(aB + aDst[j*2+0]), "r"(u0.x), "r"(u0.y), "r"(u0.z), "r"(u0.w) : "memory");
        asm volatile("st.shared.v4.b32 [%0], {%1,%2,%3,%4};" ::
          "r"(aB + aDst[j*2+1]), "r"(u1.x), "r"(u1.y), "r"(u1.z), "r"(u1.w) : "memory");
      }
    };
    auto cpB = [&](int s){
      const uint32_t bB = sB + (s & 1)*BSTG;
      const __half* bs = bSrc0 + s*64;
      #pragma unroll
      for (int u = 0; u < 4; u++)
        cpasync16(bB + bDst[u], bs + u*8);
    };

    // prologue: stage 0 fully staged before first sync
    ldgA(0);
    cpB(0);
    asm volatile("cp.async.commit_group;" ::: "memory");
    stsA(0);
    asm volatile("cp.async.wait_group 0;" ::: "memory");

    for (int s = 0; s < NSTG; s++) {
      __syncthreads();                        // stage s visible to consumers
      if (s + 1 < NSTG) {
        ldgA(s + 1);
        cpB(s + 1);
        asm volatile("cp.async.commit_group;" ::: "memory");
        stsA(s + 1);                          // into buffer freed at this sync
        asm volatile("cp.async.wait_group 0;" ::: "memory");
      }
    }
    // producers done; consumers run epilogue
  } else {
    // ==================== CONSUMER warps (8) ====================
    const int warp = t >> 5, lid = t & 31;
    const int wm = (warp >> 1) * 32;
    const int wn = (warp & 1) * 32;
    const int h16 = lid >> 4;
    const int x7  = lid & 7;
    uint32_t aLM[2], bLM[2];
    #pragma unroll
    for (int tr = 0; tr < 2; tr++)
      aLM[tr] = sA + (wm + tr*16 + (lid & 15))*128;
    #pragma unroll
    for (int ng = 0; ng < 2; ng++)
      bLM[ng] = sB + (wn + ng*16 + (lid & 15))*128;

    float acc[2][4][4];
    #pragma unroll
    for (int i = 0; i < 2; i++)
      #pragma unroll
      for (int j = 0; j < 4; j++)
        #pragma unroll
        for (int k = 0; k < 4; k++) acc[i][j][k] = 0.f;

    for (int s = 0; s < NSTG; s++) {
      __syncthreads();                        // wait stage s staged
      const uint32_t aBuf = (s & 1) * ASTG;
      const uint32_t bBuf = (s & 1) * BSTG;
      #pragma unroll
      for (int kk = 0; kk < 4; kk++) {
        const uint32_t cu16 = (uint32_t)(((kk*2 + h16) ^ x7) << 4);
        uint32_t af[2][4], br[2][4];
        #pragma unroll
        for (int tr = 0; tr < 2; tr++) ldsm4(af[tr], aLM[tr] + aBuf + cu16);
        #pragma unroll
        for (int ng = 0; ng < 2; ng++) ldsm4(br[ng], bLM[ng] + bBuf + cu16);
        #pragma unroll
        for (int tm = 0; tm < 2; tm++) {
          mma16(acc[tm][0], af[tm], br[0][0], br[0][2]);
          mma16(acc[tm][1], af[tm], br[0][1], br[0][3]);
          mma16(acc[tm][2], af[tm], br[1][0], br[1][2]);
          mma16(acc[tm][3], af[tm], br[1][1], br[1][3]);
        }
      }
    }

    // ---- epilogue ----
    const int g  = lid >> 2, t4 = lid & 3;
    #pragma unroll
    for (int tm = 0; tm < 2; tm++) {
      #pragma unroll
      for (int half = 0; half < 2; half++) {
        const int lrow = wm + tm*16 + g + half*8;
        const int m = m0 + lrow;
        const int o0 = sO0[lrow];
        const int o1 = sO1[lrow];
        const float pm = sPm[lrow];
        float* orow = out + (size_t)m * D_DIM + n0;
        #pragma unroll
        for (int tn = 0; tn < 4; tn++) {
          const int col = wn + tn*8 + t4*2;
          const int gc  = n0 + col;
          float2 e0 = *reinterpret_cast<const float2*>(ptab + o0 + gc);
          float2 e1 = *reinterpret_cast<const float2*>(ptab + o1 + gc);
          float2 r;
          r.x = acc[tm][tn][half*2 + 0] + pm * (e0.x + e1.x);
          r.y = acc[tm][tn][half*2 + 1] + pm * (e0.y + e1.y);
          *reinterpret_cast<float2*>(orow + col) = r;
        }
      }
    }
  }
}

extern "C" void kernel_launch(void* const* d_in, const int* in_sizes, int n_in,
                              void* d_out, int out_size) {
  const float* pix  = (const float*)d_in[0];
  const float* w    = (const float*)d_in[1];
  const float* tab  = (const float*)d_in[2];
  const int*   pids = (const int*)d_in[3];
  const int*   padp = (const int*)d_in[4];
  float* out = (float*)d_out;

  prep_b<<<(D_DIM*D_DIM/8)/256, 256>>>(w);   // 288 blocks

  static int smemSet = 0;
  if (!smemSet) {
    cudaFuncSetAttribute(gemma4_patch_embed,
                         cudaFuncAttributeMaxDynamicSharedMemorySize, SMEM_TOTAL);
    smemSet = 1;
  }
  dim3 grid(D_DIM / TBN, (16 * 1024) / TBM);   // (12, 128)
  gemma4_patch_embed<<<grid, THREADS, SMEM_TOTAL>>>(pix, tab, pids, padp, out);
}

// round 11
// speedup vs baseline: 1.4710x; 1.4710x over previous
#include <cuda_runtime.h>
#include <cuda_fp16.h>
#include <cstdint>

#define D_DIM 768
#define V_OFF (10240*768)
#define TBM 128
#define TBN 64
#define NSTG 12                  // K stages of 64 halfs
#define ASTG 16384               // 128 rows * 128B
#define BSTG 8192                // 64 rows * 128B
#define POS_OFF (3*(ASTG+BSTG))            // 73728
#define SMEM_TOTAL (POS_OFF + 128*12)      // 75264 -> 3 CTAs = 225792 <= 228KB

__device__ __half g_Bh[D_DIM*D_DIM];     // rn_f16(W), row-major (d, f)
__device__ __half g_Ah[16384*D_DIM];     // rn_f16(2*patch-1), (m, f)

__device__ __forceinline__ uint32_t smem_u32(const void* p){
  uint32_t a;
  asm("{ .reg .u64 t; cvta.to.shared.u64 t, %1; cvt.u32.u64 %0, t; }" : "=r"(a) : "l"(p));
  return a;
}
__device__ __forceinline__ void mma16(float* c, const uint32_t* a, uint32_t b0, uint32_t b1){
  asm volatile(
    "mma.sync.aligned.m16n8k16.row.col.f32.f16.f16.f32 "
    "{%0,%1,%2,%3},{%4,%5,%6,%7},{%8,%9},{%0,%1,%2,%3};\n"
    : "+f"(c[0]), "+f"(c[1]), "+f"(c[2]), "+f"(c[3])
    : "r"(a[0]), "r"(a[1]), "r"(a[2]), "r"(a[3]), "r"(b0), "r"(b1));
}
__device__ __forceinline__ void ldsm4(uint32_t* r, uint32_t addr){
  asm volatile("ldmatrix.sync.aligned.m8n8.x4.shared.b16 {%0,%1,%2,%3}, [%4];"
    : "=r"(r[0]), "=r"(r[1]), "=r"(r[2]), "=r"(r[3]) : "r"(addr));
}
__device__ __forceinline__ void cpasync16(uint32_t dst, const void* src){
  asm volatile("cp.async.cg.shared.global [%0], [%1], 16;"
               :: "r"(dst), "l"(src) : "memory");
}
__device__ __forceinline__ uint32_t pack2(float x, float y){
  __half2 h = __floats2half2_rn(x, y);
  return *reinterpret_cast<uint32_t*>(&h);
}

// ---- prep: fully-coalesced conversion of A (patch-major, 2x-1) and B ----
__global__ void __launch_bounds__(256) prep_ab(const float* __restrict__ pix,
                                               const float* __restrict__ w){
  const int blk = blockIdx.x;
  const int t   = threadIdx.x;
  if (blk < 1536) {
    #pragma unroll
    for (int i = 0; i < 4; i++) {
      const int q = blk*1024 + i*256 + t;       // 16B chunk of g_Ah
      const int m = q / 96, j = q - m*96;
      const int f = j*8;
      const int b = m >> 10, n = m & 1023;
      const float* src = pix + b*786432 + (f >> 8)*262144
                       + (((n >> 5) << 4) + ((f >> 4) & 15))*512
                       + (n & 31)*16 + (f & 15);
      float4 v0 = *reinterpret_cast<const float4*>(src);
      float4 v1 = *reinterpret_cast<const float4*>(src + 4);
      uint4 u;
      u.x = pack2(fmaf(2.f,v0.x,-1.f), fmaf(2.f,v0.y,-1.f));
      u.y = pack2(fmaf(2.f,v0.z,-1.f), fmaf(2.f,v0.w,-1.f));
      u.z = pack2(fmaf(2.f,v1.x,-1.f), fmaf(2.f,v1.y,-1.f));
      u.w = pack2(fmaf(2.f,v1.z,-1.f), fmaf(2.f,v1.w,-1.f));
      reinterpret_cast<uint4*>(g_Ah)[q] = u;
    }
  } else {
    #pragma unroll
    for (int i = 0; i < 4; i++) {
      const int q = (blk - 1536)*1024 + i*256 + t;
      const float4* s4 = reinterpret_cast<const float4*>(w) + q*2;
      float4 v0 = s4[0], v1 = s4[1];
      uint4 u;
      u.x = pack2(v0.x, v0.y); u.y = pack2(v0.z, v0.w);
      u.z = pack2(v1.x, v1.y); u.w = pack2(v1.z, v1.w);
      reinterpret_cast<uint4*>(g_Bh)[q] = u;
    }
  }
}

// ---- main GEMM + pos-embed: 128x64 tile, 3-stage pipeline, 3 CTAs/SM ----
__global__ void __launch_bounds__(256, 3)
gemma4_patch_embed(const float* __restrict__ ptab,     // (2,10240,768)
                   const int*   __restrict__ pids,     // (16,1024,2)
                   const int*   __restrict__ padp,     // (16,1024) bool-as-i32
                   float* __restrict__ out)            // (16,1024,768)
{
  extern __shared__ char smem[];
  const uint32_t sA = smem_u32(smem);             // 3 x ASTG
  const uint32_t sB = sA + 3*ASTG;                // 3 x BSTG
  int*   sO0 = reinterpret_cast<int*>(smem + POS_OFF);
  int*   sO1 = sO0 + 128;
  float* sPm = reinterpret_cast<float*>(sO1 + 128);
  const int t  = threadIdx.x;
  const int m0 = blockIdx.y * TBM;
  const int n0 = blockIdx.x * TBN;

  if (t < TBM) {
    const int m = m0 + t;
    int x = pids[2*m];     if (x < 0) x = 0;
    int y = pids[2*m + 1]; if (y < 0) y = 0;
    sO0[t] = x * D_DIM;
    sO1[t] = V_OFF + y * D_DIM;
    sPm[t] = (padp[m] != 0) ? 0.f : 1.f;
  }

  // ---- producers ----
  const int rA  = t >> 1;
  const int ubA = (t & 1) * 4;
  const __half* aSrc0 = g_Ah + (size_t)(m0 + rA)*D_DIM + ubA*8;
  uint32_t aDst[4];
  #pragma unroll
  for (int u = 0; u < 4; u++)
    aDst[u] = rA*128 + (((ubA + u) ^ (rA & 7)) << 4);
  const int rB  = t >> 2;
  const int ubB = (t & 3) * 2;
  const __half* bSrc0 = g_Bh + (n0 + rB)*D_DIM + ubB*8;
  uint32_t bDst[2];
  #pragma unroll
  for (int u = 0; u < 2; u++)
    bDst[u] = rB*128 + (((ubB + u) ^ (rB & 7)) << 4);

  auto issueStage = [&](int s){
    const uint32_t aB = sA + (s % 3) * ASTG;
    const uint32_t bB = sB + (s % 3) * BSTG;
    const __half* as = aSrc0 + s*64;
    const __half* bs = bSrc0 + s*64;
    #pragma unroll
    for (int u = 0; u < 4; u++)
      cpasync16(aB + aDst[u], as + u*8);
    #pragma unroll
    for (int u = 0; u < 2; u++)
      cpasync16(bB + bDst[u], bs + u*8);
  };

  // ---- consumer setup: warp grid 4(m) x 2(n); warp tile 32x32 ----
  const int warp = t >> 5, lid = t & 31;
  const int wm = (warp >> 1) * 32;
  const int wn = (warp & 1) * 32;
  const int krot = (warp & 1) << 1;    // stagger k-chunk order by warp parity
  const int h16 = lid >> 4;
  const int x7  = lid & 7;
  uint32_t aLM[2], bLM[2];
  #pragma unroll
  for (int tr = 0; tr < 2; tr++)
    aLM[tr] = sA + (wm + tr*16 + (lid & 15))*128;
  #pragma unroll
  for (int ng = 0; ng < 2; ng++)
    bLM[ng] = sB + (wn + ng*16 + (lid & 15))*128;

  float acc[2][4][4];
  #pragma unroll
  for (int i = 0; i < 2; i++)
    #pragma unroll
    for (int j = 0; j < 4; j++)
      #pragma unroll
      for (int k = 0; k < 4; k++) acc[i][j][k] = 0.f;

  issueStage(0); asm volatile("cp.async.commit_group;" ::: "memory");
  issueStage(1); asm volatile("cp.async.commit_group;" ::: "memory");

  for (int s = 0; s < NSTG; s++) {
    asm volatile("cp.async.wait_group 1;" ::: "memory");
    __syncthreads();
    if (s + 2 < NSTG) issueStage(s + 2);
    asm volatile("cp.async.commit_group;" ::: "memory");

    const uint32_t aBuf = (s % 3) * ASTG;
    const uint32_t bBuf = (s % 3) * BSTG;
    #pragma unroll
    for (int kx = 0; kx < 4; kx++) {
      const int kk = (kx + krot) & 3;
      const uint32_t cu16 = (uint32_t)(((kk*2 + h16) ^ x7) << 4);
      uint32_t af[2][4], br[2][4];
      #pragma unroll
      for (int tr = 0; tr < 2; tr++) ldsm4(af[tr], aLM[tr] + aBuf + cu16);
      #pragma unroll
      for (int ng = 0; ng < 2; ng++) ldsm4(br[ng], bLM[ng] + bBuf + cu16);
      #pragma unroll
      for (int tm = 0; tm < 2; tm++) {
        mma16(acc[tm][0], af[tm], br[0][0], br[0][2]);
        mma16(acc[tm][1], af[tm], br[0][1], br[0][3]);
        mma16(acc[tm][2], af[tm], br[1][0], br[1][2]);
        mma16(acc[tm][3], af[tm], br[1][1], br[1][3]);
      }
    }
  }

  // ---- epilogue ----
  const int g  = lid >> 2, t4 = lid & 3;
  #pragma unroll
  for (int tm = 0; tm < 2; tm++) {
    #pragma unroll
    for (int half = 0; half < 2; half++) {
      const int lrow = wm + tm*16 + g + half*8;
      const int m = m0 + lrow;
      const int o0 = sO0[lrow];
      const int o1 = sO1[lrow];
      const float pm = sPm[lrow];
      float* orow = out + (size_t)m * D_DIM + n0;
      #pragma unroll
      for (int tn = 0; tn < 4; tn++) {
        const int col = wn + tn*8 + t4*2;
        const int gc  = n0 + col;
        float2 e0 = *reinterpret_cast<const float2*>(ptab + o0 + gc);
        float2 e1 = *reinterpret_cast<const float2*>(ptab + o1 + gc);
        float2 r;
        r.x = acc[tm][tn][half*2 + 0] + pm * (e0.x + e1.x);
        r.y = acc[tm][tn][half*2 + 1] + pm * (e0.y + e1.y);
        *reinterpret_cast<float2*>(orow + col) = r;
      }
    }
  }
}

extern "C" void kernel_launch(void* const* d_in, const int* in_sizes, int n_in,
                              void* d_out, int out_size) {
  const float* pix  = (const float*)d_in[0];
  const float* w    = (const float*)d_in[1];
  const float* tab  = (const float*)d_in[2];
  const int*   pids = (const int*)d_in[3];
  const int*   padp = (const int*)d_in[4];
  float* out = (float*)d_out;

  prep_ab<<<1536 + 72, 256>>>(pix, w);

  static int smemSet = 0;
  if (!smemSet) {
    cudaFuncSetAttribute(gemma4_patch_embed,
                         cudaFuncAttributeMaxDynamicSharedMemorySize, SMEM_TOTAL);
    smemSet = 1;
  }
  dim3 grid(D_DIM / TBN, (16 * 1024) / TBM);   // (12, 128)
  gemma4_patch_embed<<<grid, 256, SMEM_TOTAL>>>(tab, pids, padp, out);
}

// round 12
// speedup vs baseline: 1.7354x; 1.1797x over previous
#include <cuda_runtime.h>
#include <cuda_fp16.h>
#include <cstdint>

#define D_DIM 768
#define V_OFF (10240*768)
#define TBM 128
#define TBN 64
#define NKT 48                   // 48 k-chunks of 16

// Fragment-ordered operands:
//  g_Af: A fragments, block (mt, kt) -> 32 lanes x 16B; idx4 = (mt*48 + kt)*32 + lane
//  g_Bf: B fragments, block (nt, kt) -> same layout
__device__ uint4 g_Af[1024*NKT*32];      // 25165824 B
__device__ uint4 g_Bf[48*NKT*32];        // 1179648 B

__device__ __forceinline__ void mma16(float* c, const uint4& a, uint32_t b0, uint32_t b1){
  asm volatile(
    "mma.sync.aligned.m16n8k16.row.col.f32.f16.f16.f32 "
    "{%0,%1,%2,%3},{%4,%5,%6,%7},{%8,%9},{%0,%1,%2,%3};\n"
    : "+f"(c[0]), "+f"(c[1]), "+f"(c[2]), "+f"(c[3])
    : "r"(a.x), "r"(a.y), "r"(a.z), "r"(a.w), "r"(b0), "r"(b1));
}
__device__ __forceinline__ uint32_t pack2(float x, float y){
  __half2 h = __floats2half2_rn(x, y);
  return *reinterpret_cast<uint32_t*>(&h);
}

// ---- prep: build fragment-ordered g_Af (2*pix-1) and g_Bf ----
// A: 6144 blocks (one 16B chunk per thread); B: 288 blocks after that.
__global__ void __launch_bounds__(256) prep_frag(const float* __restrict__ pix,
                                                 const float* __restrict__ w){
  const int blk = blockIdx.x;
  const int q = blk*256 + threadIdx.x;
  if (blk < 6144) {
    // A chunk q: lane = q&31, r = q>>5: kt = r%48, mt = r/48
    const int lane = q & 31;
    const int r = q >> 5;
    const int kt = r % NKT, mt = r / NKT;
    const int g  = lane >> 2, t4 = lane & 3;
    const int mA = mt*16 + g;          // rows mA, mA+8
    const int f0 = kt*16 + 2*t4;       // cols f0,f0+1 and f0+8,f0+9
    // pixel addr pieces for (m, f): same c,r for f0 and f0+8
    const int c  = f0 >> 8;
    const int pr = (f0 >> 4) & 15;
    const int fc = f0 & 15;
    const int bA  = mA >> 10,  nA = mA & 1023;
    const int mB_ = mA + 8;
    const int bB  = mB_ >> 10, nB = mB_ & 1023;
    const float* pa = pix + bA*786432 + c*262144 + ((nA >> 5)*16 + pr)*512 + (nA & 31)*16 + fc;
    const float* pb = pix + bB*786432 + c*262144 + ((nB >> 5)*16 + pr)*512 + (nB & 31)*16 + fc;
    float2 a0 = *reinterpret_cast<const float2*>(pa);
    float2 a2 = *reinterpret_cast<const float2*>(pa + 8);
    float2 b0 = *reinterpret_cast<const float2*>(pb);
    float2 b2 = *reinterpret_cast<const float2*>(pb + 8);
    uint4 u;
    u.x = pack2(fmaf(2.f,a0.x,-1.f), fmaf(2.f,a0.y,-1.f));
    u.y = pack2(fmaf(2.f,b0.x,-1.f), fmaf(2.f,b0.y,-1.f));
    u.z = pack2(fmaf(2.f,a2.x,-1.f), fmaf(2.f,a2.y,-1.f));
    u.w = pack2(fmaf(2.f,b2.x,-1.f), fmaf(2.f,b2.y,-1.f));
    g_Af[q] = u;
  } else {
    const int q2 = q - 6144*256;
    const int lane = q2 & 31;
    const int r = q2 >> 5;
    const int kt = r % NKT, nt = r / NKT;
    const int g  = lane >> 2, t4 = lane & 3;
    const int nA = nt*16 + g;          // d rows nA, nA+8
    const int f0 = kt*16 + 2*t4;
    const float* pa = w + nA*D_DIM + f0;
    const float* pb = w + (nA+8)*D_DIM + f0;
    float2 a0 = *reinterpret_cast<const float2*>(pa);
    float2 a2 = *reinterpret_cast<const float2*>(pa + 8);
    float2 b0 = *reinterpret_cast<const float2*>(pb);
    float2 b2 = *reinterpret_cast<const float2*>(pb + 8);
    uint4 u;
    u.x = pack2(a0.x, a0.y);
    u.y = pack2(b0.x, b0.y);
    u.z = pack2(a2.x, a2.y);
    u.w = pack2(b2.x, b2.y);
    g_Bf[q2] = u;
  }
}

// ---- main GEMM + pos-embed: zero-smem, barrier-free mainloop ----
__global__ void __launch_bounds__(256, 3)
gemma4_patch_embed(const float* __restrict__ ptab,     // (2,10240,768)
                   const int*   __restrict__ pids,     // (16,1024,2)
                   const int*   __restrict__ padp,     // (16,1024) bool-as-i32
                   float* __restrict__ out)            // (16,1024,768)
{
  __shared__ int   sO0[TBM];
  __shared__ int   sO1[TBM];
  __shared__ float sPm[TBM];
  const int t  = threadIdx.x;
  const int m0 = blockIdx.y * TBM;
  const int n0 = blockIdx.x * TBN;

  if (t < TBM) {
    const int m = m0 + t;
    int x = pids[2*m];     if (x < 0) x = 0;
    int y = pids[2*m + 1]; if (y < 0) y = 0;
    sO0[t] = x * D_DIM;
    sO1[t] = V_OFF + y * D_DIM;
    sPm[t] = (padp[m] != 0) ? 0.f : 1.f;
  }
  __syncthreads();

  const int warp = t >> 5, lid = t & 31;
  const int wm = (warp >> 1) * 32;
  const int wn = (warp & 1) * 32;
  const int mt0 = (m0 + wm) >> 4;      // A tiles mt0, mt0+1
  const int nt0 = (n0 + wn) >> 4;      // B tiles nt0, nt0+1

  const uint4* aP0 = g_Af + (size_t)mt0*NKT*32 + lid;
  const uint4* aP1 = aP0 + NKT*32;
  const uint4* bP0 = g_Bf + (size_t)nt0*NKT*32 + lid;
  const uint4* bP1 = bP0 + NKT*32;

  float acc[2][4][4];
  #pragma unroll
  for (int i = 0; i < 2; i++)
    #pragma unroll
    for (int j = 0; j < 4; j++)
      #pragma unroll
      for (int k = 0; k < 4; k++) acc[i][j][k] = 0.f;

  uint4 af[2][2], bf[2][2];
  af[0][0] = aP0[0]; af[0][1] = aP1[0];
  bf[0][0] = bP0[0]; bf[0][1] = bP1[0];

  #pragma unroll 4
  for (int kt = 0; kt < NKT; kt++) {
    const int cur = kt & 1, nxt = cur ^ 1;
    if (kt + 1 < NKT) {
      const int o = (kt + 1) * 32;
      af[nxt][0] = aP0[o]; af[nxt][1] = aP1[o];
      bf[nxt][0] = bP0[o]; bf[nxt][1] = bP1[o];
    }
    #pragma unroll
    for (int tm = 0; tm < 2; tm++) {
      mma16(acc[tm][0], af[cur][tm], bf[cur][0].x, bf[cur][0].z);
      mma16(acc[tm][1], af[cur][tm], bf[cur][0].y, bf[cur][0].w);
      mma16(acc[tm][2], af[cur][tm], bf[cur][1].x, bf[cur][1].z);
      mma16(acc[tm][3], af[cur][tm], bf[cur][1].y, bf[cur][1].w);
    }
  }

  // ---- epilogue ----
  const int g  = lid >> 2, t4 = lid & 3;
  #pragma unroll
  for (int tm = 0; tm < 2; tm++) {
    #pragma unroll
    for (int half = 0; half < 2; half++) {
      const int lrow = wm + tm*16 + g + half*8;
      const int m = m0 + lrow;
      const int o0 = sO0[lrow];
      const int o1 = sO1[lrow];
      const float pm = sPm[lrow];
      float* orow = out + (size_t)m * D_DIM + n0;
      #pragma unroll
      for (int tn = 0; tn < 4; tn++) {
        const int col = wn + tn*8 + t4*2;
        const int gc  = n0 + col;
        float2 e0 = *reinterpret_cast<const float2*>(ptab + o0 + gc);
        float2 e1 = *reinterpret_cast<const float2*>(ptab + o1 + gc);
        float2 r;
        r.x = acc[tm][tn][half*2 + 0] + pm * (e0.x + e1.x);
        r.y = acc[tm][tn][half*2 + 1] + pm * (e0.y + e1.y);
        *reinterpret_cast<float2*>(orow + col) = r;
      }
    }
  }
}

extern "C" void kernel_launch(void* const* d_in, const int* in_sizes, int n_in,
                              void* d_out, int out_size) {
  const float* pix  = (const float*)d_in[0];
  const float* w    = (const float*)d_in[1];
  const float* tab  = (const float*)d_in[2];
  const int*   pids = (const int*)d_in[3];
  const int*   padp = (const int*)d_in[4];
  float* out = (float*)d_out;

  prep_frag<<<6144 + 288, 256>>>(pix, w);

  dim3 grid(D_DIM / TBN, (16 * 1024) / TBM);   // (12, 128)
  gemma4_patch_embed<<<grid, 256>>>(tab, pids, padp, out);
}

// round 13
// speedup vs baseline: 1.7385x; 1.0018x over previous
#include <cuda_runtime.h>
#include <cuda_fp16.h>
#include <cstdint>

#define D_DIM 768
#define V_OFF (10240*768)
#define TBM 128
#define TBN 128
#define NKT 48                   // 48 k-chunks of 16

// Fragment-ordered operands (same layout as R12):
//  g_Af: A fragments, block (mt, kt) -> 32 lanes x 16B; idx4 = (mt*NKT + kt)*32 + lane
//  g_Bf: B fragments, block (nt, kt) -> same
__device__ uint4 g_Af[1024*NKT*32];
__device__ uint4 g_Bf[48*NKT*32];

__device__ __forceinline__ void mma16(float* c, const uint4& a, uint32_t b0, uint32_t b1){
  asm volatile(
    "mma.sync.aligned.m16n8k16.row.col.f32.f16.f16.f32 "
    "{%0,%1,%2,%3},{%4,%5,%6,%7},{%8,%9},{%0,%1,%2,%3};\n"
    : "+f"(c[0]), "+f"(c[1]), "+f"(c[2]), "+f"(c[3])
    : "r"(a.x), "r"(a.y), "r"(a.z), "r"(a.w), "r"(b0), "r"(b1));
}
__device__ __forceinline__ uint32_t pack2(float x, float y){
  __half2 h = __floats2half2_rn(x, y);
  return *reinterpret_cast<uint32_t*>(&h);
}

// ---- prep: build fragment-ordered g_Af (2*pix-1) and g_Bf (unchanged from R12) ----
__global__ void __launch_bounds__(256) prep_frag(const float* __restrict__ pix,
                                                 const float* __restrict__ w){
  const int blk = blockIdx.x;
  const int q = blk*256 + threadIdx.x;
  if (blk < 6144) {
    const int lane = q & 31;
    const int r = q >> 5;
    const int kt = r % NKT, mt = r / NKT;
    const int g  = lane >> 2, t4 = lane & 3;
    const int mA = mt*16 + g;
    const int f0 = kt*16 + 2*t4;
    const int c  = f0 >> 8;
    const int pr = (f0 >> 4) & 15;
    const int fc = f0 & 15;
    const int bA  = mA >> 10,  nA = mA & 1023;
    const int mB_ = mA + 8;
    const int bB  = mB_ >> 10, nB = mB_ & 1023;
    const float* pa = pix + bA*786432 + c*262144 + ((nA >> 5)*16 + pr)*512 + (nA & 31)*16 + fc;
    const float* pb = pix + bB*786432 + c*262144 + ((nB >> 5)*16 + pr)*512 + (nB & 31)*16 + fc;
    float2 a0 = *reinterpret_cast<const float2*>(pa);
    float2 a2 = *reinterpret_cast<const float2*>(pa + 8);
    float2 b0 = *reinterpret_cast<const float2*>(pb);
    float2 b2 = *reinterpret_cast<const float2*>(pb + 8);
    uint4 u;
    u.x = pack2(fmaf(2.f,a0.x,-1.f), fmaf(2.f,a0.y,-1.f));
    u.y = pack2(fmaf(2.f,b0.x,-1.f), fmaf(2.f,b0.y,-1.f));
    u.z = pack2(fmaf(2.f,a2.x,-1.f), fmaf(2.f,a2.y,-1.f));
    u.w = pack2(fmaf(2.f,b2.x,-1.f), fmaf(2.f,b2.y,-1.f));
    g_Af[q] = u;
  } else {
    const int q2 = q - 6144*256;
    const int lane = q2 & 31;
    const int r = q2 >> 5;
    const int kt = r % NKT, nt = r / NKT;
    const int g  = lane >> 2, t4 = lane & 3;
    const int nA = nt*16 + g;
    const int f0 = kt*16 + 2*t4;
    const float* pa = w + nA*D_DIM + f0;
    const float* pb = w + (nA+8)*D_DIM + f0;
    float2 a0 = *reinterpret_cast<const float2*>(pa);
    float2 a2 = *reinterpret_cast<const float2*>(pa + 8);
    float2 b0 = *reinterpret_cast<const float2*>(pb);
    float2 b2 = *reinterpret_cast<const float2*>(pb + 8);
    uint4 u;
    u.x = pack2(a0.x, a0.y);
    u.y = pack2(b0.x, b0.y);
    u.z = pack2(a2.x, a2.y);
    u.w = pack2(b2.x, b2.y);
    g_Bf[q2] = u;
  }
}

// ---- main GEMM + pos-embed: zero-smem, CTA 128x128, warp 32x64 ----
__global__ void __launch_bounds__(256, 2)
gemma4_patch_embed(const float* __restrict__ ptab,     // (2,10240,768)
                   const int*   __restrict__ pids,     // (16,1024,2)
                   const int*   __restrict__ padp,     // (16,1024) bool-as-i32
                   float* __restrict__ out)            // (16,1024,768)
{
  __shared__ int   sO0[TBM];
  __shared__ int   sO1[TBM];
  __shared__ float sPm[TBM];
  const int t  = threadIdx.x;
  const int m0 = blockIdx.y * TBM;
  const int n0 = blockIdx.x * TBN;

  if (t < TBM) {
    const int m = m0 + t;
    int x = pids[2*m];     if (x < 0) x = 0;
    int y = pids[2*m + 1]; if (y < 0) y = 0;
    sO0[t] = x * D_DIM;
    sO1[t] = V_OFF + y * D_DIM;
    sPm[t] = (padp[m] != 0) ? 0.f : 1.f;
  }
  __syncthreads();

  const int warp = t >> 5, lid = t & 31;
  const int wm = (warp >> 1) * 32;        // 4 m-positions
  const int wn = (warp & 1) * 64;         // 2 n-positions
  const int mt0 = (m0 + wm) >> 4;         // A tiles mt0, mt0+1
  const int nt0 = (n0 + wn) >> 4;         // B tiles nt0..nt0+3

  const uint4* aP0 = g_Af + (size_t)mt0*NKT*32 + lid;
  const uint4* aP1 = aP0 + NKT*32;
  const uint4* bP  = g_Bf + (size_t)nt0*NKT*32 + lid;

  float acc[2][8][4];
  #pragma unroll
  for (int i = 0; i < 2; i++)
    #pragma unroll
    for (int j = 0; j < 8; j++)
      #pragma unroll
      for (int k = 0; k < 4; k++) acc[i][j][k] = 0.f;

  uint4 af[2][2];
  af[0][0] = aP0[0]; af[0][1] = aP1[0];

  #pragma unroll 2
  for (int kt = 0; kt < NKT; kt++) {
    const int cur = kt & 1, nxt = cur ^ 1;
    const int o = kt * 32;
    uint4 bf[4];
    #pragma unroll
    for (int tn = 0; tn < 4; tn++)
      bf[tn] = bP[(size_t)tn*NKT*32 + o];
    if (kt + 1 < NKT) {
      af[nxt][0] = aP0[o + 32];
      af[nxt][1] = aP1[o + 32];
    }
    #pragma unroll
    for (int tm = 0; tm < 2; tm++) {
      #pragma unroll
      for (int tn = 0; tn < 4; tn++) {
        mma16(acc[tm][2*tn+0], af[cur][tm], bf[tn].x, bf[tn].z);
        mma16(acc[tm][2*tn+1], af[cur][tm], bf[tn].y, bf[tn].w);
      }
    }
  }

  // ---- epilogue ----
  const int g  = lid >> 2, t4 = lid & 3;
  #pragma unroll
  for (int tm = 0; tm < 2; tm++) {
    #pragma unroll
    for (int half = 0; half < 2; half++) {
      const int lrow = wm + tm*16 + g + half*8;
      const int m = m0 + lrow;
      const int o0 = sO0[lrow];
      const int o1 = sO1[lrow];
      const float pm = sPm[lrow];
      float* orow = out + (size_t)m * D_DIM + n0;
      #pragma unroll
      for (int j = 0; j < 8; j++) {
        const int col = wn + j*8 + t4*2;
        const int gc  = n0 + col;
        float2 e0 = *reinterpret_cast<const float2*>(ptab + o0 + gc);
        float2 e1 = *reinterpret_cast<const float2*>(ptab + o1 + gc);
        float2 r;
        r.x = acc[tm][j][half*2 + 0] + pm * (e0.x + e1.x);
        r.y = acc[tm][j][half*2 + 1] + pm * (e0.y + e1.y);
        *reinterpret_cast<float2*>(orow + col) = r;
      }
    }
  }
}

extern "C" void kernel_launch(void* const* d_in, const int* in_sizes, int n_in,
                              void* d_out, int out_size) {
  const float* pix  = (const float*)d_in[0];
  const float* w    = (const float*)d_in[1];
  const float* tab  = (const float*)d_in[2];
  const int*   pids = (const int*)d_in[3];
  const int*   padp = (const int*)d_in[4];
  float* out = (float*)d_out;

  prep_frag<<<6144 + 288, 256>>>(pix, w);

  dim3 grid(D_DIM / TBN, (16 * 1024) / TBM);   // (6, 128)
  gemma4_patch_embed<<<grid, 256>>>(tab, pids, padp, out);
}